// round 1
// baseline (speedup 1.0000x reference)
#include <cuda_runtime.h>

// 4-level 2D Haar DWT, fully fused.
// Input : x (64, 3, 512, 512) f32  -> treated as 192 images of 512x512
// Output: concat of levels l=0..3, each (192, 4, S, S) with S = 256 >> l
//   subband order: 0=cA, 1=cH, 2=cV, 3=cD
//
// One 256-thread block processes a 64x64 input tile:
//   load tile -> SMEM (coalesced float4)
//   L0: 32x32 quads  -> global (S=256) + cA cascade in SMEM
//   L1: 16x16 quads  -> global (S=128) + cA
//   L2:  8x8  quads  -> global (S=64)  + cA
//   L3:  4x4  quads  -> global (S=32)
// Grid: (8, 8, 192)

#define NIMG 192
#define HW   512

// element offsets of each level in the flat output
#define OFF0 0ull
#define OFF1 (OFF0 + (unsigned long long)NIMG * 4ull * 256ull * 256ull) // 50331648
#define OFF2 (OFF1 + (unsigned long long)NIMG * 4ull * 128ull * 128ull) // 62914560
#define OFF3 (OFF2 + (unsigned long long)NIMG * 4ull *  64ull *  64ull) // 66060288

__global__ __launch_bounds__(256) void fwt_kernel(const float* __restrict__ x,
                                                  float* __restrict__ out) {
    const int img = blockIdx.z;
    const int ty  = blockIdx.y;
    const int tx  = blockIdx.x;
    const int tid = threadIdx.x;

    __shared__ float sA[64][65];   // input tile / level-1 cA (16x16 reuse)
    __shared__ float sB[32][33];   // level-0 cA (32x32) / level-2 cA (8x8 reuse)

    // ---- load 64x64 tile, coalesced float4 ----
    const float* src = x + ((size_t)img * HW + (size_t)ty * 64) * HW + (size_t)tx * 64;
    #pragma unroll
    for (int i = tid; i < 64 * 16; i += 256) {
        const int r  = i >> 4;
        const int c4 = i & 15;
        float4 v = *reinterpret_cast<const float4*>(src + (size_t)r * HW + c4 * 4);
        sA[r][c4 * 4 + 0] = v.x;
        sA[r][c4 * 4 + 1] = v.y;
        sA[r][c4 * 4 + 2] = v.z;
        sA[r][c4 * 4 + 3] = v.w;
    }
    __syncthreads();

    // ---- level 0: 64x64 -> 32x32, S=256 ----
    {
        const int S = 256;
        float* base = out + OFF0 + (size_t)img * 4ull * S * S;
        #pragma unroll
        for (int q = tid; q < 32 * 32; q += 256) {
            const int qi = q >> 5, qj = q & 31;
            const float a = sA[2 * qi][2 * qj];
            const float b = sA[2 * qi][2 * qj + 1];
            const float c = sA[2 * qi + 1][2 * qj];
            const float d = sA[2 * qi + 1][2 * qj + 1];
            const float cAv = (a + b + c + d) * 0.5f;
            const float cHv = (a + b - c - d) * 0.5f;
            const float cVv = (a - b + c - d) * 0.5f;
            const float cDv = (a - b - c + d) * 0.5f;
            const int gi = ty * 32 + qi, gj = tx * 32 + qj;
            const size_t o = (size_t)gi * S + gj;
            base[o]                       = cAv;
            base[(size_t)S * S + o]       = cHv;
            base[2ull * S * S + o]        = cVv;
            base[3ull * S * S + o]        = cDv;
            sB[qi][qj] = cAv;
        }
    }
    __syncthreads();

    // ---- level 1: 32x32 -> 16x16, S=128 ----
    {
        const int S = 128;
        float* base = out + OFF1 + (size_t)img * 4ull * S * S;
        const int qi = tid >> 4, qj = tid & 15;   // exactly 256 quads
        const float a = sB[2 * qi][2 * qj];
        const float b = sB[2 * qi][2 * qj + 1];
        const float c = sB[2 * qi + 1][2 * qj];
        const float d = sB[2 * qi + 1][2 * qj + 1];
        const float cAv = (a + b + c + d) * 0.5f;
        const float cHv = (a + b - c - d) * 0.5f;
        const float cVv = (a - b + c - d) * 0.5f;
        const float cDv = (a - b - c + d) * 0.5f;
        const int gi = ty * 16 + qi, gj = tx * 16 + qj;
        const size_t o = (size_t)gi * S + gj;
        base[o]                 = cAv;
        base[(size_t)S * S + o] = cHv;
        base[2ull * S * S + o]  = cVv;
        base[3ull * S * S + o]  = cDv;
        sA[qi][qj] = cAv;   // sA no longer read at full res; safe after sync
    }
    __syncthreads();

    // ---- level 2: 16x16 -> 8x8, S=64 ----
    {
        const int S = 64;
        float* base = out + OFF2 + (size_t)img * 4ull * S * S;
        if (tid < 64) {
            const int qi = tid >> 3, qj = tid & 7;
            const float a = sA[2 * qi][2 * qj];
            const float b = sA[2 * qi][2 * qj + 1];
            const float c = sA[2 * qi + 1][2 * qj];
            const float d = sA[2 * qi + 1][2 * qj + 1];
            const float cAv = (a + b + c + d) * 0.5f;
            const float cHv = (a + b - c - d) * 0.5f;
            const float cVv = (a - b + c - d) * 0.5f;
            const float cDv = (a - b - c + d) * 0.5f;
            const int gi = ty * 8 + qi, gj = tx * 8 + qj;
            const size_t o = (size_t)gi * S + gj;
            base[o]                 = cAv;
            base[(size_t)S * S + o] = cHv;
            base[2ull * S * S + o]  = cVv;
            base[3ull * S * S + o]  = cDv;
            sB[qi][qj] = cAv;   // sB level-0 cA already consumed; safe after sync
        }
    }
    __syncthreads();

    // ---- level 3: 8x8 -> 4x4, S=32 ----
    {
        const int S = 32;
        float* base = out + OFF3 + (size_t)img * 4ull * S * S;
        if (tid < 16) {
            const int qi = tid >> 2, qj = tid & 3;
            const float a = sB[2 * qi][2 * qj];
            const float b = sB[2 * qi][2 * qj + 1];
            const float c = sB[2 * qi + 1][2 * qj];
            const float d = sB[2 * qi + 1][2 * qj + 1];
            const float cAv = (a + b + c + d) * 0.5f;
            const float cHv = (a + b - c - d) * 0.5f;
            const float cVv = (a - b + c - d) * 0.5f;
            const float cDv = (a - b - c + d) * 0.5f;
            const int gi = ty * 4 + qi, gj = tx * 4 + qj;
            const size_t o = (size_t)gi * S + gj;
            base[o]                 = cAv;
            base[(size_t)S * S + o] = cHv;
            base[2ull * S * S + o]  = cVv;
            base[3ull * S * S + o]  = cDv;
        }
    }
}

extern "C" void kernel_launch(void* const* d_in, const int* in_sizes, int n_in,
                              void* d_out, int out_size) {
    const float* x = (const float*)d_in[0];
    float* out     = (float*)d_out;
    dim3 grid(8, 8, NIMG);
    fwt_kernel<<<grid, 256>>>(x, out);
}

// round 2
// speedup vs baseline: 1.0004x; 1.0004x over previous
#include <cuda_runtime.h>

// 4-level 2D Haar DWT, fully fused, register-level level-0.
// Input : x (64, 3, 512, 512) f32 -> 192 images of 512x512
// Output: concat of levels l=0..3, each (192, 4, S, S), S = 256 >> l
//   subband order: 0=cA, 1=cH, 2=cV, 3=cD
//
// Block = 256 threads, tile = 64x64 input. Level 0 reads global directly
// (4x LDG.128 / thread) and writes float4 per subband; only the 32x32 cA
// cascades through SMEM for levels 1-3 (all float4 stores).
// Grid: (8, 8, 192)

#define NIMG 192
#define HW   512

#define OFF0 0ull
#define OFF1 (OFF0 + (unsigned long long)NIMG * 4ull * 256ull * 256ull)
#define OFF2 (OFF1 + (unsigned long long)NIMG * 4ull * 128ull * 128ull)
#define OFF3 (OFF2 + (unsigned long long)NIMG * 4ull *  64ull *  64ull)

// butterfly for one quad
#define HAAR(a, b, c, d, cA, cH, cV, cD)        \
    do {                                        \
        float s0 = (a) + (b), d0 = (a) - (b);   \
        float s1 = (c) + (d), d1 = (c) - (d);   \
        (cA) = (s0 + s1) * 0.5f;                \
        (cH) = (s0 - s1) * 0.5f;                \
        (cV) = (d0 + d1) * 0.5f;                \
        (cD) = (d0 - d1) * 0.5f;                \
    } while (0)

__global__ __launch_bounds__(256) void fwt_kernel(const float* __restrict__ x,
                                                  float* __restrict__ out) {
    const int img = blockIdx.z;
    const int ty  = blockIdx.y;
    const int tx  = blockIdx.x;
    const int tid = threadIdx.x;

    __shared__ float sB[32][33];  // level-0 cA
    __shared__ float sC[16][17];  // level-1 cA
    __shared__ float sD[8][9];    // level-2 cA

    // ---- level 0: direct global -> registers -> global, S=256 ----
    {
        const int qi  = tid >> 3;   // 0..31 quad row
        const int qjg = tid & 7;    // group of 4 quads -> input cols qjg*8..+7

        const float* src = x + ((size_t)img * HW + (size_t)ty * 64 + 2 * qi) * HW
                             + (size_t)tx * 64 + qjg * 8;
        const float4 r0a = *reinterpret_cast<const float4*>(src);
        const float4 r0b = *reinterpret_cast<const float4*>(src + 4);
        const float4 r1a = *reinterpret_cast<const float4*>(src + HW);
        const float4 r1b = *reinterpret_cast<const float4*>(src + HW + 4);

        float4 cA4, cH4, cV4, cD4;
        HAAR(r0a.x, r0a.y, r1a.x, r1a.y, cA4.x, cH4.x, cV4.x, cD4.x);
        HAAR(r0a.z, r0a.w, r1a.z, r1a.w, cA4.y, cH4.y, cV4.y, cD4.y);
        HAAR(r0b.x, r0b.y, r1b.x, r1b.y, cA4.z, cH4.z, cV4.z, cD4.z);
        HAAR(r0b.z, r0b.w, r1b.z, r1b.w, cA4.w, cH4.w, cV4.w, cD4.w);

        const int S = 256;
        float* base = out + OFF0 + (size_t)img * 4ull * S * S;
        const int gi = ty * 32 + qi, gj = tx * 32 + qjg * 4;
        const size_t o = (size_t)gi * S + gj;
        *reinterpret_cast<float4*>(base + o)                 = cA4;
        *reinterpret_cast<float4*>(base + (size_t)S * S + o) = cH4;
        *reinterpret_cast<float4*>(base + 2ull * S * S + o)  = cV4;
        *reinterpret_cast<float4*>(base + 3ull * S * S + o)  = cD4;

        sB[qi][qjg * 4 + 0] = cA4.x;
        sB[qi][qjg * 4 + 1] = cA4.y;
        sB[qi][qjg * 4 + 2] = cA4.z;
        sB[qi][qjg * 4 + 3] = cA4.w;
    }
    __syncthreads();

    // ---- level 1: 32x32 -> 16x16, S=128 (64 threads x 4 quads) ----
    if (tid < 64) {
        const int qi  = tid >> 2;   // 0..15
        const int qjg = tid & 3;    // cols qjg*8..+7 of sB

        float4 cA4, cH4, cV4, cD4;
        {
            const int r0 = 2 * qi, r1 = 2 * qi + 1, c0 = qjg * 8;
            HAAR(sB[r0][c0 + 0], sB[r0][c0 + 1], sB[r1][c0 + 0], sB[r1][c0 + 1],
                 cA4.x, cH4.x, cV4.x, cD4.x);
            HAAR(sB[r0][c0 + 2], sB[r0][c0 + 3], sB[r1][c0 + 2], sB[r1][c0 + 3],
                 cA4.y, cH4.y, cV4.y, cD4.y);
            HAAR(sB[r0][c0 + 4], sB[r0][c0 + 5], sB[r1][c0 + 4], sB[r1][c0 + 5],
                 cA4.z, cH4.z, cV4.z, cD4.z);
            HAAR(sB[r0][c0 + 6], sB[r0][c0 + 7], sB[r1][c0 + 6], sB[r1][c0 + 7],
                 cA4.w, cH4.w, cV4.w, cD4.w);
        }

        const int S = 128;
        float* base = out + OFF1 + (size_t)img * 4ull * S * S;
        const int gi = ty * 16 + qi, gj = tx * 16 + qjg * 4;
        const size_t o = (size_t)gi * S + gj;
        *reinterpret_cast<float4*>(base + o)                 = cA4;
        *reinterpret_cast<float4*>(base + (size_t)S * S + o) = cH4;
        *reinterpret_cast<float4*>(base + 2ull * S * S + o)  = cV4;
        *reinterpret_cast<float4*>(base + 3ull * S * S + o)  = cD4;

        sC[qi][qjg * 4 + 0] = cA4.x;
        sC[qi][qjg * 4 + 1] = cA4.y;
        sC[qi][qjg * 4 + 2] = cA4.z;
        sC[qi][qjg * 4 + 3] = cA4.w;
    }
    __syncthreads();

    // ---- level 2: 16x16 -> 8x8, S=64 (16 threads x 4 quads) ----
    if (tid < 16) {
        const int qi  = tid >> 1;   // 0..7
        const int qjg = tid & 1;    // cols qjg*8..+7 of sC

        float4 cA4, cH4, cV4, cD4;
        {
            const int r0 = 2 * qi, r1 = 2 * qi + 1, c0 = qjg * 8;
            HAAR(sC[r0][c0 + 0], sC[r0][c0 + 1], sC[r1][c0 + 0], sC[r1][c0 + 1],
                 cA4.x, cH4.x, cV4.x, cD4.x);
            HAAR(sC[r0][c0 + 2], sC[r0][c0 + 3], sC[r1][c0 + 2], sC[r1][c0 + 3],
                 cA4.y, cH4.y, cV4.y, cD4.y);
            HAAR(sC[r0][c0 + 4], sC[r0][c0 + 5], sC[r1][c0 + 4], sC[r1][c0 + 5],
                 cA4.z, cH4.z, cV4.z, cD4.z);
            HAAR(sC[r0][c0 + 6], sC[r0][c0 + 7], sC[r1][c0 + 6], sC[r1][c0 + 7],
                 cA4.w, cH4.w, cV4.w, cD4.w);
        }

        const int S = 64;
        float* base = out + OFF2 + (size_t)img * 4ull * S * S;
        const int gi = ty * 8 + qi, gj = tx * 8 + qjg * 4;
        const size_t o = (size_t)gi * S + gj;
        *reinterpret_cast<float4*>(base + o)                 = cA4;
        *reinterpret_cast<float4*>(base + (size_t)S * S + o) = cH4;
        *reinterpret_cast<float4*>(base + 2ull * S * S + o)  = cV4;
        *reinterpret_cast<float4*>(base + 3ull * S * S + o)  = cD4;

        sD[qi][qjg * 4 + 0] = cA4.x;
        sD[qi][qjg * 4 + 1] = cA4.y;
        sD[qi][qjg * 4 + 2] = cA4.z;
        sD[qi][qjg * 4 + 3] = cA4.w;
    }
    __syncthreads();

    // ---- level 3: 8x8 -> 4x4, S=32 (4 threads x 4 quads) ----
    if (tid < 4) {
        const int qi = tid;  // 0..3, full 4-quad row

        float4 cA4, cH4, cV4, cD4;
        {
            const int r0 = 2 * qi, r1 = 2 * qi + 1;
            HAAR(sD[r0][0], sD[r0][1], sD[r1][0], sD[r1][1], cA4.x, cH4.x, cV4.x, cD4.x);
            HAAR(sD[r0][2], sD[r0][3], sD[r1][2], sD[r1][3], cA4.y, cH4.y, cV4.y, cD4.y);
            HAAR(sD[r0][4], sD[r0][5], sD[r1][4], sD[r1][5], cA4.z, cH4.z, cV4.z, cD4.z);
            HAAR(sD[r0][6], sD[r0][7], sD[r1][6], sD[r1][7], cA4.w, cH4.w, cV4.w, cD4.w);
        }

        const int S = 32;
        float* base = out + OFF3 + (size_t)img * 4ull * S * S;
        const int gi = ty * 4 + qi, gj = tx * 4;
        const size_t o = (size_t)gi * S + gj;
        *reinterpret_cast<float4*>(base + o)                 = cA4;
        *reinterpret_cast<float4*>(base + (size_t)S * S + o) = cH4;
        *reinterpret_cast<float4*>(base + 2ull * S * S + o)  = cV4;
        *reinterpret_cast<float4*>(base + 3ull * S * S + o)  = cD4;
    }
}

extern "C" void kernel_launch(void* const* d_in, const int* in_sizes, int n_in,
                              void* d_out, int out_size) {
    const float* x = (const float*)d_in[0];
    float* out     = (float*)d_out;
    dim3 grid(8, 8, NIMG);
    fwt_kernel<<<grid, 256>>>(x, out);
}